// round 17
// baseline (speedup 1.0000x reference)
#include <cuda_runtime.h>
#include <cuda_bf16.h>

typedef unsigned int u32;

#define B_ 2048
#define I_ 512
#define O_ 256
#define NSEG 7
#define NKF (NSEG * 32)      // 224 k16 frags in big-K
#define NMT (B_ / 16)        // 128 m16 tiles
#define NPAIR 28             // 224 kf / 8 per pair
#define APITCH 522           // padded a-row pitch (f32) in prep smem

// Operands pre-swizzled into mma fragment layout:
// AF[((mtile*NKF + kf)*32 + lane)] = {a0,a1,a2,a3} of m16k16 frag
// BF[((kf*16 + n16t)*32 + lane)]   = {b0,b1 of n8t even, b0,b1 of n8t odd}
__device__ __align__(256) uint4 AF[NMT * NKF * 32];   // 14.68MB
__device__ __align__(256) uint4 BF[NKF * 16 * 32];    // 1.84MB

__device__ __forceinline__ u32 pack2(float lo, float hi) {
    __nv_bfloat162 p = __floats2bfloat162_rn(lo, hi);
    return *(u32*)&p;
}
__device__ __forceinline__ float tA(int seg, float v) {
    if (seg <= 1) return v;                                            // ah (both hi segs)
    if (seg == 2) return v - __bfloat162float(__float2bfloat16_rn(v)); // al
    float v2 = v * v;
    if (seg == 3) return v2;
    if (seg == 4) return v2 * v;
    if (seg == 5) return v2 * v2;
    return v2 * v2 * v;
}
__device__ __forceinline__ float tB(int seg, float v) {
    if (seg == 0 || seg == 2) return v;                                // wh
    if (seg == 1) return v - __bfloat162float(__float2bfloat16_rn(v)); // wl
    float v2 = v * v;
    if (seg == 3) return v2 * 0.5f;
    if (seg == 4) return v2 * v * (1.0f / 3.0f);
    if (seg == 5) return v2 * v2 * 0.25f;
    return v2 * v2 * v * 0.2f;
}

// ---------------- K1: prep fragment-major AF + BF ----------------
__global__ __launch_bounds__(256) void l0_prep(
    const float* __restrict__ x, const float* __restrict__ w,
    const float* __restrict__ qz)
{
    extern __shared__ float shm[];
    const int tid = threadIdx.x;

    if (blockIdx.x < NMT) {
        // ---- A: block = m16 tile; a = 1 - x*z; 7 seg transforms -> frags.
        float* zs = shm;          // [512]
        float* as = shm + 512;    // [16][APITCH]
        const int b = blockIdx.x;
        for (int i = tid; i < I_; i += 256) {
            float q = qz[i];
            float pi = 1.0f / (1.0f + expf(-q));
            zs[i] = fminf(fmaxf(fmaf(pi, 1.2f, -0.1f), 0.0f), 1.0f);
        }
        __syncthreads();
        {
            const int r = tid & 15, ic = tid >> 4;
            const float* xr = x + (b * 16 + r) * I_ + ic * 32;
            const float* zr = zs + ic * 32;
            float* ar = as + r * APITCH + ic * 32;
#pragma unroll
            for (int j4 = 0; j4 < 8; ++j4) {
                float4 xv = *(const float4*)(xr + j4 * 4);
                float4 zv = *(const float4*)(zr + j4 * 4);
                ar[j4 * 4 + 0] = fmaf(-xv.x, zv.x, 1.0f);
                ar[j4 * 4 + 1] = fmaf(-xv.y, zv.y, 1.0f);
                ar[j4 * 4 + 2] = fmaf(-xv.z, zv.z, 1.0f);
                ar[j4 * 4 + 3] = fmaf(-xv.w, zv.w, 1.0f);
            }
        }
        __syncthreads();
        const int L = tid & 31, r = L >> 2, c2 = (L & 3) * 2;
#pragma unroll 1
        for (int j = 0; j < 28; ++j) {
            const int f = (tid >> 5) + 8 * j;       // kf 0..223 (seg-uniform per warp)
            const int seg = f >> 5;
            const int i0 = (f & 31) * 16 + c2;
            float2 a0 = *(const float2*)(as + r * APITCH + i0);
            float2 a1 = *(const float2*)(as + (r + 8) * APITCH + i0);
            float2 a2 = *(const float2*)(as + r * APITCH + i0 + 8);
            float2 a3 = *(const float2*)(as + (r + 8) * APITCH + i0 + 8);
            AF[((size_t)b * NKF + f) * 32 + L] = make_uint4(
                pack2(tA(seg, a0.x), tA(seg, a0.y)),
                pack2(tA(seg, a1.x), tA(seg, a1.y)),
                pack2(tA(seg, a2.x), tA(seg, a2.y)),
                pack2(tA(seg, a3.x), tA(seg, a3.y)));
        }
    } else {
        // ---- B: block = (k0, n0) 64x64 tile of w -> frags for 7 segs.
        float (*wbuf)[65] = (float(*)[65])shm;
        const int bt = blockIdx.x - NMT;
        const int k0 = (bt >> 2) * 64, n0 = (bt & 3) * 64;
#pragma unroll
        for (int j = 0; j < 16; ++j) {
            int idx = tid + 256 * j;
            wbuf[idx >> 6][idx & 63] = w[(k0 + (idx >> 6)) * O_ + n0 + (idx & 63)];
        }
        __syncthreads();
        const int L = tid & 31;
#pragma unroll 1
        for (int j = 0; j < 14; ++j) {
            const int fr = (tid >> 5) + 8 * j;      // 0..111 (seg-uniform per warp)
            const int seg = fr >> 4, rem = fr & 15;
            const int klq = rem >> 2, n16q = rem & 3;
            const int kk = klq * 16 + (L & 3) * 2;
            const int nn0 = n16q * 16 + (L >> 2);
            float w00 = wbuf[kk][nn0],         w01 = wbuf[kk + 1][nn0];
            float w10 = wbuf[kk + 8][nn0],     w11 = wbuf[kk + 9][nn0];
            float w20 = wbuf[kk][nn0 + 8],     w21 = wbuf[kk + 1][nn0 + 8];
            float w30 = wbuf[kk + 8][nn0 + 8], w31 = wbuf[kk + 9][nn0 + 8];
            const int kf = seg * 32 + (k0 >> 4) + klq;
            const int n16t = (n0 >> 4) + n16q;
            BF[(kf * 16 + n16t) * 32 + L] = make_uint4(
                pack2(tB(seg, w00), tB(seg, w01)),
                pack2(tB(seg, w10), tB(seg, w11)),
                pack2(tB(seg, w20), tB(seg, w21)),
                pack2(tB(seg, w30), tB(seg, w31)));
        }
    }
}

// ---------------- K2: smem-free GEMM, 8-way warp split-K ----------------
__global__ __launch_bounds__(256, 2) void l0_gemm(float* __restrict__ out)
{
    __shared__ float psum[8][32][32];   // 32KB, epilogue only

    const int tid = threadIdx.x, lane = tid & 31, wid = tid >> 5;
    const int wn = wid >> 2, wk = wid & 3;
    const int m0 = (blockIdx.x >> 2) * 32, n0 = (blockIdx.x & 3) * 64;
    const int mtile0 = m0 >> 4;
    const int n16t0 = (n0 >> 4) + wn * 2;

    const uint4* aP = AF + (size_t)mtile0 * NKF * 32 + lane;  // + kf*32 (+NKF*32 for mt1)
    const uint4* bP = BF + n16t0 * 32 + lane;                 // + kf*512 (+32 for n16t+1)

    uint4 aB[2][2][2];   // [buf][ks][mt]
    uint4 bB[2][2][2];   // [buf][ks][ntp]

#define LOADP(p, buf)                                                        \
    {                                                                        \
        const int kfA = 8 * (p) + wk, kfB = kfA + 4;                         \
        aB[buf][0][0] = aP[kfA * 32];                                        \
        aB[buf][0][1] = aP[kfA * 32 + NKF * 32];                             \
        aB[buf][1][0] = aP[kfB * 32];                                        \
        aB[buf][1][1] = aP[kfB * 32 + NKF * 32];                             \
        bB[buf][0][0] = bP[kfA * 512];                                       \
        bB[buf][0][1] = bP[kfA * 512 + 32];                                  \
        bB[buf][1][0] = bP[kfB * 512];                                       \
        bB[buf][1][1] = bP[kfB * 512 + 32];                                  \
    }

    float acc[2][4][4];
#pragma unroll
    for (int mt = 0; mt < 2; ++mt)
#pragma unroll
        for (int nt = 0; nt < 4; ++nt)
#pragma unroll
            for (int e = 0; e < 4; ++e) acc[mt][nt][e] = 0.0f;

#define COMP(cb)                                                             \
    {                                                                        \
        _Pragma("unroll") for (int ks = 0; ks < 2; ++ks)                     \
        _Pragma("unroll") for (int mt = 0; mt < 2; ++mt)                     \
        _Pragma("unroll") for (int ntp = 0; ntp < 2; ++ntp) {                \
            asm volatile(                                                    \
                "mma.sync.aligned.m16n8k16.row.col.f32.bf16.bf16.f32 "       \
                "{%0,%1,%2,%3}, {%4,%5,%6,%7}, {%8,%9}, {%0,%1,%2,%3};"      \
                : "+f"(acc[mt][2 * ntp][0]), "+f"(acc[mt][2 * ntp][1]),      \
                  "+f"(acc[mt][2 * ntp][2]), "+f"(acc[mt][2 * ntp][3])       \
                : "r"(aB[cb][ks][mt].x), "r"(aB[cb][ks][mt].y),              \
                  "r"(aB[cb][ks][mt].z), "r"(aB[cb][ks][mt].w),              \
                  "r"(bB[cb][ks][ntp].x), "r"(bB[cb][ks][ntp].y));           \
            asm volatile(                                                    \
                "mma.sync.aligned.m16n8k16.row.col.f32.bf16.bf16.f32 "       \
                "{%0,%1,%2,%3}, {%4,%5,%6,%7}, {%8,%9}, {%0,%1,%2,%3};"      \
                : "+f"(acc[mt][2 * ntp + 1][0]), "+f"(acc[mt][2 * ntp + 1][1]), \
                  "+f"(acc[mt][2 * ntp + 1][2]), "+f"(acc[mt][2 * ntp + 1][3]) \
                : "r"(aB[cb][ks][mt].x), "r"(aB[cb][ks][mt].y),              \
                  "r"(aB[cb][ks][mt].z), "r"(aB[cb][ks][mt].w),              \
                  "r"(bB[cb][ks][ntp].z), "r"(bB[cb][ks][ntp].w));           \
        }                                                                    \
    }

    LOADP(0, 0);
#pragma unroll 1
    for (int p = 0; p < NPAIR; p += 2) {
        LOADP(p + 1, 1);
        COMP(0);
        if (p + 2 < NPAIR) LOADP(p + 2, 0);
        COMP(1);
    }

    // Epilogue: stash per-warp 32x32 partials, reduce over wk in fixed order.
    {
        float* pw = &psum[wid][0][0];
        const int r0 = lane >> 2, c0 = (lane & 3) * 2;
#pragma unroll
        for (int mt = 0; mt < 2; ++mt)
#pragma unroll
            for (int nt = 0; nt < 4; ++nt) {
                float* t = pw + (mt * 16 + r0) * 32 + nt * 8 + c0;
                t[0] = acc[mt][nt][0];
                t[1] = acc[mt][nt][1];
                t[256] = acc[mt][nt][2];   // +8 rows
                t[257] = acc[mt][nt][3];
            }
    }
    __syncthreads();
#pragma unroll
    for (int j = 0; j < 8; ++j) {
        int idx = tid + 256 * j;          // 0..2047 over the 32x64 tile
        int m = idx >> 6, n = idx & 63;
        int s4 = (n >> 5) * 4, nc = n & 31;
        float s = psum[s4][m][nc] + psum[s4 + 1][m][nc] +
                  psum[s4 + 2][m][nc] + psum[s4 + 3][m][nc];
        out[(m0 + m) * O_ + n0 + n] = expf(-s);
    }
}

extern "C" void kernel_launch(void* const* d_in, const int* in_sizes, int n_in,
                              void* d_out, int out_size) {
    const float* x = nullptr;
    const float* w = nullptr;
    const float* qz = nullptr;
    for (int i = 0; i < n_in; ++i) {
        if (in_sizes[i] == B_ * I_)      x  = (const float*)d_in[i];
        else if (in_sizes[i] == I_ * O_) w  = (const float*)d_in[i];
        else if (in_sizes[i] == I_)      qz = (const float*)d_in[i];
    }
    const int prep_smem = (512 + 16 * APITCH) * sizeof(float);   // 35.5KB (>= wbuf 16.6KB)
    l0_prep<<<NMT + 32, 256, prep_smem>>>(x, w, qz);
    l0_gemm<<<(B_ / 32) * (O_ / 64), 256>>>((float*)d_out);
}